// round 2
// baseline (speedup 1.0000x reference)
#include <cuda_runtime.h>

#define NN 100000
#define NE 600000
#define HID 128
#define OUTD 64

// ---------------- scratch (device globals; no allocations allowed) ----------
__device__ float g_h[4 * NN * HID];       // hidden states h0..h3 (204.8 MB)
__device__ float g_t[NN * HID];           // t = h + agg           (51.2 MB)
__device__ float g_Wt[4 * HID * HID];     // transposed W_in + 3 convs
__device__ float g_WtO[512 * OUTD];       // transposed W_out
__device__ int   g_off[NN + 1];
__device__ int   g_deg[NN];
__device__ int   g_cur[NN];
__device__ int   g_srcs[NE];
__device__ int   g_src[NE];
__device__ int   g_dst[NE];
__device__ int   g_is64;
__device__ int   g_bsum[128];

// ---------------- edge dtype detection + decode -----------------------------
// If edge_index is int64 (little-endian, values in [0,100000)), every odd
// 32-bit word of the first 64 entries is zero. If int32, those words are
// themselves edge values, which are ~never all zero (values uniform in
// [0,100000)). Deterministic for fixed input.
__global__ void k_detect(const unsigned* __restrict__ raw) {
    if (threadIdx.x == 0) {
        int is64 = 1;
        for (int i = 1; i < 128; i += 2)
            if (raw[i] != 0u) { is64 = 0; break; }
        g_is64 = is64;
    }
}

__global__ void k_decode(const void* __restrict__ raw) {
    int e = blockIdx.x * blockDim.x + threadIdx.x;
    if (e >= NE) return;
    if (g_is64) {
        const long long* p = (const long long*)raw;
        g_src[e] = (int)p[e];
        g_dst[e] = (int)p[NE + e];
    } else {
        const int* p = (const int*)raw;
        g_src[e] = p[e];
        g_dst[e] = p[NE + e];
    }
}

// ---------------- CSR build (counting sort by dst) ---------------------------
__global__ void k_zero() {
    int i = blockIdx.x * blockDim.x + threadIdx.x;
    if (i < NN) { g_deg[i] = 0; g_cur[i] = 0; }
}

__global__ void k_count() {
    int e = blockIdx.x * blockDim.x + threadIdx.x;
    if (e < NE) atomicAdd(&g_deg[g_dst[e]], 1);
}

// inclusive block scan of g_deg (1024/block), block sums -> g_bsum
__global__ void k_scan1() {
    __shared__ int sh[1024];
    int i = blockIdx.x * 1024 + threadIdx.x;
    int v = (i < NN) ? g_deg[i] : 0;
    sh[threadIdx.x] = v;
    __syncthreads();
    for (int s = 1; s < 1024; s <<= 1) {
        int a = (threadIdx.x >= (unsigned)s) ? sh[threadIdx.x - s] : 0;
        __syncthreads();
        sh[threadIdx.x] += a;
        __syncthreads();
    }
    if (i < NN) g_deg[i] = sh[threadIdx.x];
    if (threadIdx.x == 1023) g_bsum[blockIdx.x] = sh[1023];
}

// exclusive scan of block sums (nb <= 128)
__global__ void k_scan2(int nb) {
    __shared__ int sh[128];
    int t = threadIdx.x;
    sh[t] = (t < nb) ? g_bsum[t] : 0;
    __syncthreads();
    if (t == 0) {
        int acc = 0;
        for (int i = 0; i < nb; i++) { int v = sh[i]; sh[i] = acc; acc += v; }
    }
    __syncthreads();
    if (t < nb) g_bsum[t] = sh[t];
}

__global__ void k_scan3() {
    int i = blockIdx.x * 1024 + threadIdx.x;
    if (i < NN) g_off[i + 1] = g_deg[i] + g_bsum[blockIdx.x];
    if (i == 0) g_off[0] = 0;
}

__global__ void k_fill() {
    int e = blockIdx.x * blockDim.x + threadIdx.x;
    if (e >= NE) return;
    int d = g_dst[e];
    int p = atomicAdd(&g_cur[d], 1);
    g_srcs[g_off[d] + p] = g_src[e];
}

// ---------------- weight transposes ------------------------------------------
__global__ void k_transpose128(const float* __restrict__ W, float* __restrict__ Wt) {
    int j = blockIdx.x, k = threadIdx.x;   // 128 blocks x 128 threads
    Wt[k * 128 + j] = W[j * 128 + k];
}

__global__ void k_transpose_out(const float* __restrict__ W) {
    int o = blockIdx.x, k = threadIdx.x;   // 64 blocks x 512 threads
    g_WtO[k * OUTD + o] = W[o * 512 + k];
}

// ---------------- aggregation: t[n] = h[n] + sum_{src->n} h[src] -------------
// one warp per node, lane = 4-float slice of the 128-dim feature
__global__ void k_agg(const float* __restrict__ h) {
    int gw   = (blockIdx.x * blockDim.x + threadIdx.x) >> 5;
    int lane = threadIdx.x & 31;
    if (gw >= NN) return;
    const float4* hv = (const float4*)h;
    float4 acc = hv[gw * 32 + lane];       // self term (GIN eps=0)
    int s0 = g_off[gw], s1 = g_off[gw + 1];
    for (int j = s0; j < s1; j++) {
        int s = g_srcs[j];
        float4 v = hv[s * 32 + lane];
        acc.x += v.x; acc.y += v.y; acc.z += v.z; acc.w += v.w;
    }
    ((float4*)g_t)[gw * 32 + lane] = acc;
}

// ---------------- GEMM: C[N,128] = A[N,128] * W^T + b ------------------------
// tile 64 rows x 128 cols, 256 threads, thread tile 8x4, K in 2 chunks of 64
__global__ void k_gemm128(const float* __restrict__ A, const float* __restrict__ Wt,
                          const float* __restrict__ bias, float* __restrict__ C,
                          int nrows) {
    __shared__ float As[64][64];    // 16 KB
    __shared__ float Ws[64][128];   // 32 KB
    int tid = threadIdx.x;
    int tx = tid & 31;              // cols tx*4 .. tx*4+3
    int ty = tid >> 5;              // rows ty*8 .. ty*8+7
    int row0 = blockIdx.x * 64;

    float acc[8][4];
#pragma unroll
    for (int r = 0; r < 8; r++)
#pragma unroll
        for (int c = 0; c < 4; c++) acc[r][c] = 0.f;

    for (int kc = 0; kc < 2; kc++) {
        __syncthreads();
        // load A tile: 64x64 floats = 1024 float4
        for (int i = tid; i < 64 * 16; i += 256) {
            int r = i >> 4, c4 = i & 15;
            int gr = row0 + r;
            float4 v = (gr < nrows) ? ((const float4*)A)[gr * 32 + kc * 16 + c4]
                                    : make_float4(0.f, 0.f, 0.f, 0.f);
            ((float4*)&As[r][0])[c4] = v;
        }
        // load W tile: 64x128 floats = 2048 float4
        for (int i = tid; i < 64 * 32; i += 256) {
            int k = i >> 5, c4 = i & 31;
            ((float4*)&Ws[k][0])[c4] = ((const float4*)Wt)[(kc * 64 + k) * 32 + c4];
        }
        __syncthreads();

        for (int k = 0; k < 64; k += 4) {
            float4 a[8], w[4];
#pragma unroll
            for (int r = 0; r < 8; r++) a[r] = *(float4*)&As[ty * 8 + r][k];
#pragma unroll
            for (int kk = 0; kk < 4; kk++) w[kk] = *(float4*)&Ws[k + kk][tx * 4];
#pragma unroll
            for (int r = 0; r < 8; r++) {
                float ar[4] = {a[r].x, a[r].y, a[r].z, a[r].w};
#pragma unroll
                for (int kk = 0; kk < 4; kk++) {
                    acc[r][0] += ar[kk] * w[kk].x;
                    acc[r][1] += ar[kk] * w[kk].y;
                    acc[r][2] += ar[kk] * w[kk].z;
                    acc[r][3] += ar[kk] * w[kk].w;
                }
            }
        }
    }

    float b0 = bias[tx * 4 + 0], b1 = bias[tx * 4 + 1];
    float b2 = bias[tx * 4 + 2], b3 = bias[tx * 4 + 3];
#pragma unroll
    for (int r = 0; r < 8; r++) {
        int gr = row0 + ty * 8 + r;
        if (gr < nrows) {
            float4 v = make_float4(acc[r][0] + b0, acc[r][1] + b1,
                                   acc[r][2] + b2, acc[r][3] + b3);
            ((float4*)C)[gr * 32 + tx] = v;
        }
    }
}

// ---------------- final: out = softmax(cat(h0..h3) @ Wout^T + b) -------------
// tile 64 rows x 64 cols (full output width), 256 threads, thread tile 4x4
__global__ void k_gemm_out(const float* __restrict__ hbase,
                           const float* __restrict__ bias,
                           float* __restrict__ out, int nrows) {
    __shared__ float As[64][64];   // 16 KB
    __shared__ float Ws[64][64];   // 16 KB
    int tid = threadIdx.x;
    int tx = tid & 15;             // cols tx*4 .. +3
    int ty = tid >> 4;             // rows ty*4 .. +3
    int row0 = blockIdx.x * 64;

    float acc[4][4];
#pragma unroll
    for (int r = 0; r < 4; r++)
#pragma unroll
        for (int c = 0; c < 4; c++) acc[r][c] = 0.f;

    for (int kc = 0; kc < 8; kc++) {           // K = 512 in chunks of 64
        const float* Asrc = hbase + (size_t)(kc >> 1) * NN * HID;
        int colv4 = (kc & 1) * 16;             // 64-float offset within the 128-col h
        __syncthreads();
        for (int i = tid; i < 64 * 16; i += 256) {
            int r = i >> 4, c4 = i & 15;
            int gr = row0 + r;
            float4 v = (gr < nrows) ? ((const float4*)Asrc)[gr * 32 + colv4 + c4]
                                    : make_float4(0.f, 0.f, 0.f, 0.f);
            ((float4*)&As[r][0])[c4] = v;
        }
        for (int i = tid; i < 64 * 16; i += 256) {
            int k = i >> 4, c4 = i & 15;
            ((float4*)&Ws[k][0])[c4] = ((const float4*)g_WtO)[(kc * 64 + k) * 16 + c4];
        }
        __syncthreads();

        for (int k = 0; k < 64; k += 4) {
            float4 a[4], w[4];
#pragma unroll
            for (int r = 0; r < 4; r++) a[r] = *(float4*)&As[ty * 4 + r][k];
#pragma unroll
            for (int kk = 0; kk < 4; kk++) w[kk] = *(float4*)&Ws[k + kk][tx * 4];
#pragma unroll
            for (int r = 0; r < 4; r++) {
                float ar[4] = {a[r].x, a[r].y, a[r].z, a[r].w};
#pragma unroll
                for (int kk = 0; kk < 4; kk++) {
                    acc[r][0] += ar[kk] * w[kk].x;
                    acc[r][1] += ar[kk] * w[kk].y;
                    acc[r][2] += ar[kk] * w[kk].z;
                    acc[r][3] += ar[kk] * w[kk].w;
                }
            }
        }
    }

    float b0 = bias[tx * 4 + 0], b1 = bias[tx * 4 + 1];
    float b2 = bias[tx * 4 + 2], b3 = bias[tx * 4 + 3];

    // softmax over the 64 cols of each row; cols are spread over 16 lanes (tx),
    // lanes with the same ty live in the same 16-lane shuffle group.
#pragma unroll
    for (int r = 0; r < 4; r++) {
        float v0 = acc[r][0] + b0, v1 = acc[r][1] + b1;
        float v2 = acc[r][2] + b2, v3 = acc[r][3] + b3;
        float m = fmaxf(fmaxf(v0, v1), fmaxf(v2, v3));
#pragma unroll
        for (int off = 1; off < 16; off <<= 1)
            m = fmaxf(m, __shfl_xor_sync(0xffffffffu, m, off));
        float e0 = __expf(v0 - m), e1 = __expf(v1 - m);
        float e2 = __expf(v2 - m), e3 = __expf(v3 - m);
        float s = e0 + e1 + e2 + e3;
#pragma unroll
        for (int off = 1; off < 16; off <<= 1)
            s += __shfl_xor_sync(0xffffffffu, s, off);
        float inv = 1.0f / s;
        int gr = row0 + ty * 4 + r;
        if (gr < nrows)
            ((float4*)out)[gr * 16 + tx] =
                make_float4(e0 * inv, e1 * inv, e2 * inv, e3 * inv);
    }
}

// ---------------- host -------------------------------------------------------
extern "C" void kernel_launch(void* const* d_in, const int* in_sizes, int n_in,
                              void* d_out, int out_size) {
    const float* x       = (const float*)d_in[0];
    const void*  ei      = d_in[1];
    const float* W_in    = (const float*)d_in[2];
    const float* b_in    = (const float*)d_in[3];
    const float* W_convs = (const float*)d_in[4];
    const float* b_convs = (const float*)d_in[5];
    const float* W_out   = (const float*)d_in[6];
    const float* b_out   = (const float*)d_in[7];
    float* out = (float*)d_out;

    float *hbase, *tbuf, *wt;
    cudaGetSymbolAddress((void**)&hbase, g_h);
    cudaGetSymbolAddress((void**)&tbuf, g_t);
    cudaGetSymbolAddress((void**)&wt, g_Wt);

    const int EB = (NE + 255) / 256;
    const int NB = (NN + 255) / 256;
    const int SB = (NN + 1023) / 1024;   // 98

    // edge decode + CSR build
    k_detect<<<1, 32>>>((const unsigned*)ei);
    k_decode<<<EB, 256>>>(ei);
    k_zero<<<NB, 256>>>();
    k_count<<<EB, 256>>>();
    k_scan1<<<SB, 1024>>>();
    k_scan2<<<1, 128>>>(SB);
    k_scan3<<<SB, 1024>>>();
    k_fill<<<EB, 256>>>();

    // weight transposes
    k_transpose128<<<128, 128>>>(W_in, wt);
    for (int l = 0; l < 3; l++)
        k_transpose128<<<128, 128>>>(W_convs + (size_t)l * 128 * 128,
                                     wt + (size_t)(1 + l) * 128 * 128);
    k_transpose_out<<<64, 512>>>(W_out);

    const int GB = (NN + 63) / 64;       // 1563

    // input projection: h0 = x @ W_in^T + b_in
    k_gemm128<<<GB, 256>>>(x, wt, b_in, hbase, NN);

    // 3 GIN layers
    for (int l = 0; l < 3; l++) {
        k_agg<<<(NN * 32 + 255) / 256, 256>>>(hbase + (size_t)l * NN * HID);
        k_gemm128<<<GB, 256>>>(tbuf, wt + (size_t)(1 + l) * 128 * 128,
                               b_convs + (size_t)l * HID,
                               hbase + (size_t)(l + 1) * NN * HID, NN);
    }

    // output projection + fused softmax
    k_gemm_out<<<GB, 256>>>(hbase, b_out, out, NN);
}

// round 4
// speedup vs baseline: 1.5457x; 1.5457x over previous
#include <cuda_runtime.h>
#include <cuda_bf16.h>
#include <cstdint>

#define NN 100000
#define NE 600000
#define HID 128
#define OUTD 64

// ---------------- scratch (device globals; no allocations allowed) ----------
__device__ float g_h[4 * NN * HID];               // hidden states h0..h3
__device__ float g_t[NN * HID];                   // t = h + agg
__device__ __nv_bfloat16 g_Wb[4 * 2 * HID * HID]; // per layer: hi[128][128], lo[128][128]
__device__ __nv_bfloat16 g_WoB[2 * OUTD * 512];   // W_out: hi[64][512], lo[64][512]
__device__ int   g_off[NN + 1];
__device__ int   g_deg[NN];
__device__ int   g_cur[NN];
__device__ int   g_srcs[NE];
__device__ int   g_src[NE];
__device__ int   g_dst[NE];
__device__ int   g_is64;
__device__ int   g_bsum[128];

// ---------------- helpers -----------------------------------------------------
// fp32 -> bf16 hi/lo split of a float4 (hi = rn(x), lo = rn(x - hi))
__device__ __forceinline__ void split4(float4 v, uint2& hi, uint2& lo) {
    __nv_bfloat16 hx = __float2bfloat16_rn(v.x);
    __nv_bfloat16 hy = __float2bfloat16_rn(v.y);
    __nv_bfloat16 hz = __float2bfloat16_rn(v.z);
    __nv_bfloat16 hw = __float2bfloat16_rn(v.w);
    hi.x = (uint32_t)__bfloat16_as_ushort(hx) | ((uint32_t)__bfloat16_as_ushort(hy) << 16);
    hi.y = (uint32_t)__bfloat16_as_ushort(hz) | ((uint32_t)__bfloat16_as_ushort(hw) << 16);
    __nv_bfloat16 lx = __float2bfloat16_rn(v.x - __bfloat162float(hx));
    __nv_bfloat16 ly = __float2bfloat16_rn(v.y - __bfloat162float(hy));
    __nv_bfloat16 lz = __float2bfloat16_rn(v.z - __bfloat162float(hz));
    __nv_bfloat16 lw = __float2bfloat16_rn(v.w - __bfloat162float(hw));
    lo.x = (uint32_t)__bfloat16_as_ushort(lx) | ((uint32_t)__bfloat16_as_ushort(ly) << 16);
    lo.y = (uint32_t)__bfloat16_as_ushort(lz) | ((uint32_t)__bfloat16_as_ushort(lw) << 16);
}

// base-ISA tensor core mma (sm_80+): D[16x8] += A[16x16] * B[16x8], bf16 in, f32 acc
__device__ __forceinline__ void mma_bf16(float* c, uint32_t a0, uint32_t a1,
                                         uint32_t a2, uint32_t a3,
                                         uint32_t b0, uint32_t b1) {
    asm volatile(
        "mma.sync.aligned.m16n8k16.row.col.f32.bf16.bf16.f32 "
        "{%0,%1,%2,%3},{%4,%5,%6,%7},{%8,%9},{%0,%1,%2,%3};"
        : "+f"(c[0]), "+f"(c[1]), "+f"(c[2]), "+f"(c[3])
        : "r"(a0), "r"(a1), "r"(a2), "r"(a3), "r"(b0), "r"(b1));
}

// smem row stride for 64-bf16 rows: 128B data + 16B pad -> conflict-free frag loads
#define SA 144

// ---------------- edge dtype detection + decode -----------------------------
__global__ void k_detect(const unsigned* __restrict__ raw) {
    if (threadIdx.x == 0) {
        int is64 = 1;
        for (int i = 1; i < 128; i += 2)
            if (raw[i] != 0u) { is64 = 0; break; }
        g_is64 = is64;
    }
}

__global__ void k_decode(const void* __restrict__ raw) {
    int e = blockIdx.x * blockDim.x + threadIdx.x;
    if (e >= NE) return;
    if (g_is64) {
        const long long* p = (const long long*)raw;
        g_src[e] = (int)p[e];
        g_dst[e] = (int)p[NE + e];
    } else {
        const int* p = (const int*)raw;
        g_src[e] = p[e];
        g_dst[e] = p[NE + e];
    }
}

// ---------------- CSR build (counting sort by dst) ---------------------------
__global__ void k_zero() {
    int i = blockIdx.x * blockDim.x + threadIdx.x;
    if (i < NN) { g_deg[i] = 0; g_cur[i] = 0; }
}
__global__ void k_count() {
    int e = blockIdx.x * blockDim.x + threadIdx.x;
    if (e < NE) atomicAdd(&g_deg[g_dst[e]], 1);
}
__global__ void k_scan1() {
    __shared__ int sh[1024];
    int i = blockIdx.x * 1024 + threadIdx.x;
    int v = (i < NN) ? g_deg[i] : 0;
    sh[threadIdx.x] = v;
    __syncthreads();
    for (int s = 1; s < 1024; s <<= 1) {
        int a = (threadIdx.x >= (unsigned)s) ? sh[threadIdx.x - s] : 0;
        __syncthreads();
        sh[threadIdx.x] += a;
        __syncthreads();
    }
    if (i < NN) g_deg[i] = sh[threadIdx.x];
    if (threadIdx.x == 1023) g_bsum[blockIdx.x] = sh[1023];
}
__global__ void k_scan2(int nb) {
    __shared__ int sh[128];
    int t = threadIdx.x;
    sh[t] = (t < nb) ? g_bsum[t] : 0;
    __syncthreads();
    if (t == 0) {
        int acc = 0;
        for (int i = 0; i < nb; i++) { int v = sh[i]; sh[i] = acc; acc += v; }
    }
    __syncthreads();
    if (t < nb) g_bsum[t] = sh[t];
}
__global__ void k_scan3() {
    int i = blockIdx.x * 1024 + threadIdx.x;
    if (i < NN) g_off[i + 1] = g_deg[i] + g_bsum[blockIdx.x];
    if (i == 0) g_off[0] = 0;
}
__global__ void k_fill() {
    int e = blockIdx.x * blockDim.x + threadIdx.x;
    if (e >= NE) return;
    int d = g_dst[e];
    int p = atomicAdd(&g_cur[d], 1);
    g_srcs[g_off[d] + p] = g_src[e];
}

// ---------------- weight preconversion (plain bf16 hi/lo images) ------------
__global__ void k_prepW(const float* __restrict__ W_in, const float* __restrict__ W_convs) {
    int idx = blockIdx.x * blockDim.x + threadIdx.x;   // 4*128*32
    if (idx >= 4 * 128 * 32) return;
    int l = idx >> 12;
    int rem = idx & 4095;
    int j = rem >> 5;
    int k4 = rem & 31;
    const float* W = (l == 0) ? W_in : (W_convs + (size_t)(l - 1) * 128 * 128);
    float4 v = ((const float4*)W)[j * 32 + k4];
    uint2 hp, lp; split4(v, hp, lp);
    char* base = (char*)(g_Wb + (size_t)l * 2 * 16384);
    *(uint2*)(base + j * 256 + k4 * 8) = hp;            // hi[j][k4*4..]
    *(uint2*)(base + 32768 + j * 256 + k4 * 8) = lp;    // lo
}

__global__ void k_prepWo(const float* __restrict__ W_out) {
    int idx = blockIdx.x * blockDim.x + threadIdx.x;   // 64*128
    if (idx >= 64 * 128) return;
    int j = idx >> 7;
    int k4 = idx & 127;
    float4 v = ((const float4*)W_out)[j * 128 + k4];
    uint2 hp, lp; split4(v, hp, lp);
    char* base = (char*)g_WoB;
    *(uint2*)(base + j * 1024 + k4 * 8) = hp;           // hi[j][k4*4..] (512 cols)
    *(uint2*)(base + 65536 + j * 1024 + k4 * 8) = lp;   // lo
}

// ---------------- aggregation: t[n] = h[n] + sum_{src->n} h[src] -------------
__global__ void k_agg(const float* __restrict__ h) {
    int gw   = (blockIdx.x * blockDim.x + threadIdx.x) >> 5;
    int lane = threadIdx.x & 31;
    if (gw >= NN) return;
    const float4* hv = (const float4*)h;
    float4 acc = hv[gw * 32 + lane];
    int s0 = g_off[gw], s1 = g_off[gw + 1];
    for (int j = s0; j < s1; j++) {
        int s = g_srcs[j];
        float4 v = hv[s * 32 + lane];
        acc.x += v.x; acc.y += v.y; acc.z += v.z; acc.w += v.w;
    }
    ((float4*)g_t)[gw * 32 + lane] = acc;
}

// ---------------- HMMA GEMM: C[N,128] = A[N,128] @ W^T + b -------------------
// CTA: 128-row tile, 8 warps x 16 rows. K chunks of 64 in smem (bf16 hi/lo,
// stride-144 rows). 3 passes: Ah*Wh + Ah*Wl + Al*Wh.
// smem: AH@0 (18432), AL@18432, WH@36864, WL@55296; total 73728
__global__ void __launch_bounds__(256, 2)
k_gemm_hmma(const float* __restrict__ A, const __nv_bfloat16* __restrict__ Wimg,
            const float* __restrict__ bias, float* __restrict__ C, int nrows) {
    extern __shared__ char sm[];
    char* AH = sm;
    char* AL = sm + 18432;
    char* WH = sm + 36864;
    char* WL = sm + 55296;
    int tid = threadIdx.x, wid = tid >> 5, lane = tid & 31;
    int quad = lane >> 2, qi = lane & 3;
    int row0 = blockIdx.x * 128;

    float acc[16][4];
#pragma unroll
    for (int t = 0; t < 16; t++)
#pragma unroll
        for (int c = 0; c < 4; c++) acc[t][c] = 0.f;

    const int abase = (wid * 16 + quad) * SA + qi * 4;

    for (int kc = 0; kc < 2; kc++) {
        if (kc) __syncthreads();
        // W chunk: hi+lo, rows 0..127, cols kc*64..  (src row stride 256B)
        for (int i = tid; i < 2048; i += 256) {
            int m = i >> 10, j = (i & 1023) >> 3, seg = i & 7;
            uint4 v = *(const uint4*)((const char*)Wimg + m * 32768 + j * 256 + kc * 128 + seg * 16);
            *(uint4*)((m ? WL : WH) + j * SA + seg * 16) = v;
        }
        // A chunk: 128 rows x 64 cols fp32 -> bf16 hi/lo
        for (int i = tid; i < 2048; i += 256) {
            int r = i >> 4, k4 = i & 15;
            int gr = row0 + r;
            float4 v = (gr < nrows) ? ((const float4*)A)[(size_t)gr * 32 + kc * 16 + k4]
                                    : make_float4(0.f, 0.f, 0.f, 0.f);
            uint2 hp, lp; split4(v, hp, lp);
            *(uint2*)(AH + r * SA + k4 * 8) = hp;
            *(uint2*)(AL + r * SA + k4 * 8) = lp;
        }
        __syncthreads();

#pragma unroll
        for (int pass = 0; pass < 3; pass++) {
            const char* Ab = (pass == 2) ? AL : AH;
            const char* Wb = (pass == 1) ? WL : WH;
#pragma unroll
            for (int s = 0; s < 4; s++) {
                uint32_t a0 = *(const uint32_t*)(Ab + abase + s * 32);
                uint32_t a1 = *(const uint32_t*)(Ab + abase + 8 * SA + s * 32);
                uint32_t a2 = *(const uint32_t*)(Ab + abase + s * 32 + 16);
                uint32_t a3 = *(const uint32_t*)(Ab + abase + 8 * SA + s * 32 + 16);
#pragma unroll
                for (int t = 0; t < 16; t++) {
                    const char* wp = Wb + (t * 8 + quad) * SA + qi * 4 + s * 32;
                    uint32_t b0 = *(const uint32_t*)wp;
                    uint32_t b1 = *(const uint32_t*)(wp + 16);
                    mma_bf16(acc[t], a0, a1, a2, a3, b0, b1);
                }
            }
        }
    }

    int rA = row0 + wid * 16 + quad, rB = rA + 8;
#pragma unroll
    for (int t = 0; t < 16; t++) {
        int c = t * 8 + qi * 2;
        float bx = bias[c], by = bias[c + 1];
        if (rA < nrows) {
            float2 o = make_float2(acc[t][0] + bx, acc[t][1] + by);
            *(float2*)&C[(size_t)rA * 128 + c] = o;
        }
        if (rB < nrows) {
            float2 o = make_float2(acc[t][2] + bx, acc[t][3] + by);
            *(float2*)&C[(size_t)rB * 128 + c] = o;
        }
    }
}

// ---------------- final: out = softmax(cat(h0..h3) @ Wout^T + b) -------------
// K=512 in 8 chunks of 64 (chunk kc reads h_{kc/2}, col half kc&1). N=64.
// smem: AH@0, AL@18432, WH@36864 (9216), WL@46080; total 55296
__global__ void __launch_bounds__(256, 2)
k_final_hmma(const float* __restrict__ hbase, const float* __restrict__ bias,
             float* __restrict__ out, int nrows) {
    extern __shared__ char sm[];
    char* AH = sm;
    char* AL = sm + 18432;
    char* WH = sm + 36864;
    char* WL = sm + 46080;
    int tid = threadIdx.x, wid = tid >> 5, lane = tid & 31;
    int quad = lane >> 2, qi = lane & 3;
    int row0 = blockIdx.x * 128;

    float acc[8][4];
#pragma unroll
    for (int t = 0; t < 8; t++)
#pragma unroll
        for (int c = 0; c < 4; c++) acc[t][c] = 0.f;

    const int abase = (wid * 16 + quad) * SA + qi * 4;

    for (int kc = 0; kc < 8; kc++) {
        if (kc) __syncthreads();
        // W chunk: hi+lo, rows 0..63 of W_out, cols kc*64.. (src row stride 1024B)
        for (int i = tid; i < 1024; i += 256) {
            int m = i >> 9, j = (i & 511) >> 3, seg = i & 7;
            uint4 v = *(const uint4*)((const char*)g_WoB + m * 65536 + j * 1024 + kc * 128 + seg * 16);
            *(uint4*)((m ? WL : WH) + j * SA + seg * 16) = v;
        }
        // A chunk from hidden state kc/2, column half kc&1
        const float4* Ag = (const float4*)(hbase + (size_t)(kc >> 1) * NN * HID);
        int cb = (kc & 1) * 16;
        for (int i = tid; i < 2048; i += 256) {
            int r = i >> 4, k4 = i & 15;
            int gr = row0 + r;
            float4 v = (gr < nrows) ? Ag[(size_t)gr * 32 + cb + k4]
                                    : make_float4(0.f, 0.f, 0.f, 0.f);
            uint2 hp, lp; split4(v, hp, lp);
            *(uint2*)(AH + r * SA + k4 * 8) = hp;
            *(uint2*)(AL + r * SA + k4 * 8) = lp;
        }
        __syncthreads();

#pragma unroll
        for (int pass = 0; pass < 3; pass++) {
            const char* Ab = (pass == 2) ? AL : AH;
            const char* Wb = (pass == 1) ? WL : WH;
#pragma unroll
            for (int s = 0; s < 4; s++) {
                uint32_t a0 = *(const uint32_t*)(Ab + abase + s * 32);
                uint32_t a1 = *(const uint32_t*)(Ab + abase + 8 * SA + s * 32);
                uint32_t a2 = *(const uint32_t*)(Ab + abase + s * 32 + 16);
                uint32_t a3 = *(const uint32_t*)(Ab + abase + 8 * SA + s * 32 + 16);
#pragma unroll
                for (int t = 0; t < 8; t++) {
                    const char* wp = Wb + (t * 8 + quad) * SA + qi * 4 + s * 32;
                    uint32_t b0 = *(const uint32_t*)wp;
                    uint32_t b1 = *(const uint32_t*)(wp + 16);
                    mma_bf16(acc[t], a0, a1, a2, a3, b0, b1);
                }
            }
        }
    }

    // bias + softmax. Row rA data: acc[t][0..1]; row rB: acc[t][2..3]; each row
    // spread over its 4-lane quad (lanes differ in qi only).
    int rA = row0 + wid * 16 + quad, rB = rA + 8;
    float vA[16], vB[16];
#pragma unroll
    for (int t = 0; t < 8; t++) {
        int c = t * 8 + qi * 2;
        float bx = bias[c], by = bias[c + 1];
        vA[2 * t] = acc[t][0] + bx; vA[2 * t + 1] = acc[t][1] + by;
        vB[2 * t] = acc[t][2] + bx; vB[2 * t + 1] = acc[t][3] + by;
    }
    float mA = vA[0], mB = vB[0];
#pragma unroll
    for (int j = 1; j < 16; j++) { mA = fmaxf(mA, vA[j]); mB = fmaxf(mB, vB[j]); }
    mA = fmaxf(mA, __shfl_xor_sync(0xffffffffu, mA, 1));
    mA = fmaxf(mA, __shfl_xor_sync(0xffffffffu, mA, 2));
    mB = fmaxf(mB, __shfl_xor_sync(0xffffffffu, mB, 1));
    mB = fmaxf(mB, __shfl_xor_sync(0xffffffffu, mB, 2));
    float sA = 0.f, sB = 0.f;
#pragma unroll
    for (int j = 0; j < 16; j++) {
        vA[j] = __expf(vA[j] - mA); sA += vA[j];
        vB[j] = __expf(vB[j] - mB); sB += vB[j];
    }
    sA += __shfl_xor_sync(0xffffffffu, sA, 1);
    sA += __shfl_xor_sync(0xffffffffu, sA, 2);
    sB += __shfl_xor_sync(0xffffffffu, sB, 1);
    sB += __shfl_xor_sync(0xffffffffu, sB, 2);
    float iA = 1.0f / sA, iB = 1.0f / sB;
#pragma unroll
    for (int t = 0; t < 8; t++) {
        int c = t * 8 + qi * 2;
        if (rA < nrows)
            *(float2*)&out[(size_t)rA * 64 + c] =
                make_float2(vA[2 * t] * iA, vA[2 * t + 1] * iA);
        if (rB < nrows)
            *(float2*)&out[(size_t)rB * 64 + c] =
                make_float2(vB[2 * t] * iB, vB[2 * t + 1] * iB);
    }
}

// ---------------- host -------------------------------------------------------
extern "C" void kernel_launch(void* const* d_in, const int* in_sizes, int n_in,
                              void* d_out, int out_size) {
    const float* x       = (const float*)d_in[0];
    const void*  ei      = d_in[1];
    const float* W_in    = (const float*)d_in[2];
    const float* b_in    = (const float*)d_in[3];
    const float* W_convs = (const float*)d_in[4];
    const float* b_convs = (const float*)d_in[5];
    const float* W_out   = (const float*)d_in[6];
    const float* b_out   = (const float*)d_in[7];
    float* out = (float*)d_out;

    float *hbase, *tbuf;
    __nv_bfloat16* wb;
    cudaGetSymbolAddress((void**)&hbase, g_h);
    cudaGetSymbolAddress((void**)&tbuf, g_t);
    cudaGetSymbolAddress((void**)&wb, g_Wb);

    const int SMEM_G = 73728;
    const int SMEM_F = 55296;
    cudaFuncSetAttribute(k_gemm_hmma,  cudaFuncAttributeMaxDynamicSharedMemorySize, SMEM_G);
    cudaFuncSetAttribute(k_final_hmma, cudaFuncAttributeMaxDynamicSharedMemorySize, SMEM_F);

    const int EB = (NE + 255) / 256;
    const int NB = (NN + 255) / 256;
    const int SB = (NN + 1023) / 1024;

    // edge decode + CSR build
    k_detect<<<1, 32>>>((const unsigned*)ei);
    k_decode<<<EB, 256>>>(ei);
    k_zero<<<NB, 256>>>();
    k_count<<<EB, 256>>>();
    k_scan1<<<SB, 1024>>>();
    k_scan2<<<1, 128>>>(SB);
    k_scan3<<<SB, 1024>>>();
    k_fill<<<EB, 256>>>();

    // weight preconversion (bf16 hi/lo images)
    k_prepW<<<64, 256>>>(W_in, W_convs);
    k_prepWo<<<32, 256>>>(W_out);

    const int GB = (NN + 127) / 128;   // 782

    // input projection
    k_gemm_hmma<<<GB, 256, SMEM_G>>>(x, wb, b_in, hbase, NN);

    // 3 GIN layers
    for (int l = 0; l < 3; l++) {
        k_agg<<<(NN * 32 + 255) / 256, 256>>>(hbase + (size_t)l * NN * HID);
        k_gemm_hmma<<<GB, 256, SMEM_G>>>(tbuf, wb + (size_t)(1 + l) * 2 * 16384,
                                         b_convs + (size_t)l * HID,
                                         hbase + (size_t)(l + 1) * NN * HID, NN);
    }

    // output projection + fused softmax
    k_final_hmma<<<GB, 256, SMEM_F>>>(hbase, b_out, out, NN);
}